// round 12
// baseline (speedup 1.0000x reference)
#include <cuda_runtime.h>
#include <cuda_bf16.h>
#include <cstdint>
#include <cstddef>

#define NN   50000
#define EE   800000
#define HDIM 128
#define GG   512
#define OUTD 64
#define BN_EPS 1e-5f

// ---------------- device scratch (no allocation allowed) ----------------
__device__ __align__(16) float g_bufX[NN * HDIM];
__device__ __align__(16) float g_bufA[NN * HDIM];
__device__ __align__(16) float g_bufB[NN * HDIM];
__device__ __align__(16) float g_pool[GG * HDIM];
__device__ __align__(16) float g_head[GG * HDIM];
__device__ __align__(16) float g_stats[2 * HDIM];
// CSR scratch (deg zero at load; scan_kernel re-zeroes after use)
__device__ int g_deg[NN];
__device__ int g_rowptr[NN + 1];
__device__ int g_cursor[NN];
__device__ int g_csr[EE];

// ---------------- helpers ----------------
__device__ __forceinline__ void red_add_f4(float4* addr, float4 v) {
    asm volatile("red.global.add.v4.f32 [%0], {%1,%2,%3,%4};"
                 :: "l"(addr), "f"(v.x), "f"(v.y), "f"(v.z), "f"(v.w)
                 : "memory");
}

__device__ __forceinline__ void cp_async16(void* smem_dst, const void* gsrc) {
    unsigned d = (unsigned)__cvta_generic_to_shared(smem_dst);
    asm volatile("cp.async.cg.shared.global [%0], [%1], 16;"
                 :: "r"(d), "l"(gsrc));
}
#define CP_COMMIT()  asm volatile("cp.async.commit_group;")
#define CP_WAIT0()   asm volatile("cp.async.wait_group 0;")

__device__ __forceinline__ uint32_t smem_u32(const void* p) {
    uint32_t a;
    asm("{ .reg .u64 t; cvta.to.shared.u64 t, %1; cvt.u32.u64 %0, t; }"
        : "=r"(a) : "l"(p));
    return a;
}

// bf16 mma: D(16x8,f32) += A(16x16,bf16 row) * B(16x8,bf16 col)
__device__ __forceinline__ void mma_bf16(float* d, const unsigned* a,
                                         const unsigned* b) {
    asm volatile(
        "mma.sync.aligned.m16n8k16.row.col.f32.bf16.bf16.f32 "
        "{%0,%1,%2,%3}, {%4,%5,%6,%7}, {%8,%9}, {%0,%1,%2,%3};"
        : "+f"(d[0]), "+f"(d[1]), "+f"(d[2]), "+f"(d[3])
        : "r"(a[0]), "r"(a[1]), "r"(a[2]), "r"(a[3]), "r"(b[0]), "r"(b[1]));
}

__device__ __forceinline__ void ldmx4(unsigned* r, uint32_t addr) {
    asm volatile(
        "ldmatrix.sync.aligned.m8n8.x4.shared.b16 {%0,%1,%2,%3}, [%4];"
        : "=r"(r[0]), "=r"(r[1]), "=r"(r[2]), "=r"(r[3]) : "r"(addr));
}

__device__ __forceinline__ unsigned pack_bf16x2(__nv_bfloat16 a, __nv_bfloat16 b) {
    return ((unsigned)__bfloat16_as_ushort(b) << 16) |
           (unsigned)__bfloat16_as_ushort(a);
}
__device__ __forceinline__ void split_bf16(float v, __nv_bfloat16& hi,
                                           __nv_bfloat16& lo) {
    hi = __float2bfloat16_rn(v);
    lo = __float2bfloat16_rn(v - __bfloat162float(hi));
}

// ---------------- CSR build kernels ----------------
__global__ void hist_kernel(const int* __restrict__ dst, int* __restrict__ deg) {
    int e = blockIdx.x * blockDim.x + threadIdx.x;
    if (e < EE) atomicAdd(&deg[dst[e]], 1);
}

__global__ void scan_kernel(int* __restrict__ deg,
                            int* __restrict__ rowptr,
                            int* __restrict__ cursor) {
    __shared__ int ssum[1024];
    const int T = 1024, CH = (NN + T - 1) / T;
    int t = threadIdx.x;
    int begin = t * CH;
    int end = begin + CH; if (end > NN) end = NN;
    int s = 0;
    for (int i = begin; i < end; i++) s += deg[i];
    ssum[t] = s;
    __syncthreads();
    for (int off = 1; off < T; off <<= 1) {
        int v = (t >= off) ? ssum[t - off] : 0;
        __syncthreads();
        ssum[t] += v;
        __syncthreads();
    }
    int run = (t == 0) ? 0 : ssum[t - 1];
    for (int i = begin; i < end; i++) {
        rowptr[i] = run;
        cursor[i] = run;
        run += deg[i];
        deg[i] = 0;
    }
    if (t == T - 1) rowptr[NN] = ssum[T - 1];
}

__global__ void fill_kernel(const int* __restrict__ src,
                            const int* __restrict__ dst,
                            int* __restrict__ cursor,
                            int* __restrict__ csr) {
    int e = blockIdx.x * blockDim.x + threadIdx.x;
    if (e >= EE) return;
    int pos = atomicAdd(&cursor[dst[e]], 1);
    csr[pos] = src[e];
}

// ---------------- aggregation: warp per node (R6-proven) ----------------
__global__ void gather_kernel(const float4* __restrict__ x,
                              float4* __restrict__ agg,
                              const int* __restrict__ rowptr,
                              const int* __restrict__ csr,
                              float* __restrict__ stats) {
    if (blockIdx.x == 0 && threadIdx.x < 2 * HDIM) stats[threadIdx.x] = 0.f;
    int n = blockIdx.x * 8 + (threadIdx.x >> 5);
    if (n >= NN) return;
    int lane = threadIdx.x & 31;
    int b = rowptr[n], e = rowptr[n + 1];
    float4 a0 = x[(size_t)n * 32 + lane];
    float4 a1 = make_float4(0.f, 0.f, 0.f, 0.f);
    float4 a2 = make_float4(0.f, 0.f, 0.f, 0.f);
    float4 a3 = make_float4(0.f, 0.f, 0.f, 0.f);
    int i = b;
    for (; i + 4 <= e; i += 4) {
        int s0 = csr[i], s1 = csr[i + 1], s2 = csr[i + 2], s3 = csr[i + 3];
        float4 v0 = x[(size_t)s0 * 32 + lane];
        float4 v1 = x[(size_t)s1 * 32 + lane];
        float4 v2 = x[(size_t)s2 * 32 + lane];
        float4 v3 = x[(size_t)s3 * 32 + lane];
        a0.x += v0.x; a0.y += v0.y; a0.z += v0.z; a0.w += v0.w;
        a1.x += v1.x; a1.y += v1.y; a1.z += v1.z; a1.w += v1.w;
        a2.x += v2.x; a2.y += v2.y; a2.z += v2.z; a2.w += v2.w;
        a3.x += v3.x; a3.y += v3.y; a3.z += v3.z; a3.w += v3.w;
    }
    for (; i < e; i++) {
        float4 v = x[(size_t)csr[i] * 32 + lane];
        a0.x += v.x; a0.y += v.y; a0.z += v.z; a0.w += v.w;
    }
    a0.x += a1.x + a2.x + a3.x;
    a0.y += a1.y + a2.y + a3.y;
    a0.z += a1.z + a2.z + a3.z;
    a0.w += a1.w + a2.w + a3.w;
    agg[(size_t)n * 32 + lane] = a0;
}

// ---------------- GEMM: bf16x3 MMA with ldmatrix fragments ----------------
// M x 128 @ 128 x 128 via D = Ah*Wh + Ah*Wl + Al*Wh, fp32 accum.
// PRE_BN: derive scale/shift from stats/gamma/beta in-block; apply to A load.
// Dynamic smem (bytes):
//   stageA f32 [2][128][16] @0      (16384)
//   Wraw   f32 [2][16][128] @16384  (16384)
//   Ahi  bf16 [128][24] @32768 (6144)   48B rows -> ldmatrix conflict-free
//   Alo  bf16 [128][24] @38912 (6144)
//   Wthi bf16 [128][24] @45056 (6144)   [n][k]
//   Wtlo bf16 [128][24] @51200 (6144)
//   s_scale f32[128] @57344, s_shift f32[128] @57856
#define GEMM_SMEM_BYTES 58368

template <bool PRE_BN, bool POST_RELU, bool STATS>
__global__ void __launch_bounds__(256, 2)
gemm_k128(const float* __restrict__ A, const float* __restrict__ W,
          const float* __restrict__ bias, const float* __restrict__ gamma,
          const float* __restrict__ beta, float* __restrict__ out,
          float* __restrict__ stats, int M, float invM) {
    extern __shared__ char smem[];
    float*          stageA = (float*)smem;
    float*          Wraw   = (float*)(smem + 16384);
    __nv_bfloat16*  Ahi    = (__nv_bfloat16*)(smem + 32768);
    __nv_bfloat16*  Alo    = (__nv_bfloat16*)(smem + 38912);
    __nv_bfloat16*  Wthi   = (__nv_bfloat16*)(smem + 45056);
    __nv_bfloat16*  Wtlo   = (__nv_bfloat16*)(smem + 51200);
    float*          s_scale = (float*)(smem + 57344);
    float*          s_shift = (float*)(smem + 57856);

    const int tid  = threadIdx.x;
    const int w    = tid >> 5;
    const int lane = tid & 31;
    const int grp  = lane >> 2;
    const int q    = lane & 3;
    const int mBase = (w & 3) * 32;
    const int nBase = (w >> 2) * 64;
    const int base_row = blockIdx.x * 128;

    if (PRE_BN && tid < 128) {
        float mu   = stats[tid] * invM;
        float var  = stats[128 + tid] * invM - mu * mu;
        float rstd = rsqrtf(var + BN_EPS);
        float sc   = gamma[tid] * rstd;
        s_scale[tid] = sc;
        s_shift[tid] = beta[tid] - mu * sc;
    }

    float acc[2][8][4];
#pragma unroll
    for (int mt = 0; mt < 2; mt++)
#pragma unroll
        for (int nt = 0; nt < 8; nt++)
#pragma unroll
            for (int c = 0; c < 4; c++) acc[mt][nt][c] = 0.f;

    auto issue_tile = [&](int buf, int kb) {
#pragma unroll
        for (int t = 0; t < 2; t++) {
            int idx = tid + t * 256;
            int row = idx >> 2, j = idx & 3;
            int gr  = base_row + row;
            int cgr = gr < M ? gr : 0;
            cp_async16(stageA + buf * 2048 + row * 16 + 4 * j,
                       A + (size_t)cgr * 128 + kb + 4 * j);
        }
#pragma unroll
        for (int t = 0; t < 2; t++) {
            int idx = tid + t * 256;
            int kk = idx >> 5, c = idx & 31;
            cp_async16(Wraw + buf * 2048 + kk * 128 + 4 * c,
                       W + (size_t)(kb + kk) * 128 + 4 * c);
        }
        CP_COMMIT();
    };

    issue_tile(0, 0);

    // ldmatrix lane addressing (row within 16, k-half)
    const uint32_t aHi_u = smem_u32(Ahi), aLo_u = smem_u32(Alo);
    const uint32_t wHi_u = smem_u32(Wthi), wLo_u = smem_u32(Wtlo);
    const int lrow = (lane & 7) + ((lane >> 3) & 1) * 8;
    const int lkb  = (lane >> 4) * 16;     // byte offset for k-half
    uint32_t aoff[2], boff[4];
#pragma unroll
    for (int mt = 0; mt < 2; mt++)
        aoff[mt] = (uint32_t)((mBase + mt * 16 + lrow) * 48 + lkb);
#pragma unroll
    for (int ntp = 0; ntp < 4; ntp++)
        boff[ntp] = (uint32_t)((nBase + ntp * 16 + lrow) * 48 + lkb);

    for (int kb8 = 0; kb8 < 8; kb8++) {
        const int buf = kb8 & 1;
        CP_WAIT0();
        __syncthreads();          // tile visible; prev ldmatrix reads done
        if (kb8 < 7) issue_tile(buf ^ 1, (kb8 + 1) * 16);

        // A transform: f32 -> (hi,lo) bf16, padded rows, optional BN+ReLU
#pragma unroll
        for (int t = 0; t < 2; t++) {
            int idx = tid + t * 256;
            int row = idx >> 2, j = idx & 3;
            float4 v = *(const float4*)(stageA + buf * 2048 + row * 16 + 4 * j);
            if (PRE_BN) {
                int k = kb8 * 16 + 4 * j;
                v.x = fmaxf(fmaf(v.x, s_scale[k + 0], s_shift[k + 0]), 0.f);
                v.y = fmaxf(fmaf(v.y, s_scale[k + 1], s_shift[k + 1]), 0.f);
                v.z = fmaxf(fmaf(v.z, s_scale[k + 2], s_shift[k + 2]), 0.f);
                v.w = fmaxf(fmaf(v.w, s_scale[k + 3], s_shift[k + 3]), 0.f);
            }
            __nv_bfloat16 hx,lx,hy,ly,hz,lz,hw,lw;
            split_bf16(v.x,hx,lx); split_bf16(v.y,hy,ly);
            split_bf16(v.z,hz,lz); split_bf16(v.w,hw,lw);
            *(uint2*)(Ahi + row * 24 + 4 * j) =
                make_uint2(pack_bf16x2(hx,hy), pack_bf16x2(hz,hw));
            *(uint2*)(Alo + row * 24 + 4 * j) =
                make_uint2(pack_bf16x2(lx,ly), pack_bf16x2(lz,lw));
        }
        // W transform: transpose + split, padded rows
#pragma unroll
        for (int t = 0; t < 2; t++) {
            int idx = tid + t * 256;
            int c = idx & 127, jk = idx >> 7;
            float v0 = Wraw[buf * 2048 + (4*jk+0) * 128 + c];
            float v1 = Wraw[buf * 2048 + (4*jk+1) * 128 + c];
            float v2 = Wraw[buf * 2048 + (4*jk+2) * 128 + c];
            float v3 = Wraw[buf * 2048 + (4*jk+3) * 128 + c];
            __nv_bfloat16 h0,l0,h1,l1,h2,l2,h3,l3;
            split_bf16(v0,h0,l0); split_bf16(v1,h1,l1);
            split_bf16(v2,h2,l2); split_bf16(v3,h3,l3);
            *(uint2*)(Wthi + c * 24 + 4 * jk) =
                make_uint2(pack_bf16x2(h0,h1), pack_bf16x2(h2,h3));
            *(uint2*)(Wtlo + c * 24 + 4 * jk) =
                make_uint2(pack_bf16x2(l0,l1), pack_bf16x2(l2,l3));
        }
        __syncthreads();

        // fragments via ldmatrix
        unsigned ah[2][4], al[2][4], bh[4][4], bl[4][4];
#pragma unroll
        for (int mt = 0; mt < 2; mt++) {
            ldmx4(ah[mt], aHi_u + aoff[mt]);
            ldmx4(al[mt], aLo_u + aoff[mt]);
        }
#pragma unroll
        for (int ntp = 0; ntp < 4; ntp++) {
            ldmx4(bh[ntp], wHi_u + boff[ntp]);
            ldmx4(bl[ntp], wLo_u + boff[ntp]);
        }
#pragma unroll
        for (int ntp = 0; ntp < 4; ntp++) {
#pragma unroll
            for (int sub = 0; sub < 2; sub++) {
                unsigned bhx[2] = { bh[ntp][sub], bh[ntp][sub + 2] };
                unsigned blx[2] = { bl[ntp][sub], bl[ntp][sub + 2] };
                int nt = 2 * ntp + sub;
#pragma unroll
                for (int mt = 0; mt < 2; mt++) {
                    mma_bf16(acc[mt][nt], ah[mt], bhx);
                    mma_bf16(acc[mt][nt], ah[mt], blx);
                    mma_bf16(acc[mt][nt], al[mt], bhx);
                }
            }
        }
    }

    // ---- epilogue ----
    float csum[8][2], csq[8][2];
    if (STATS) {
#pragma unroll
        for (int nt = 0; nt < 8; nt++) {
            csum[nt][0] = csum[nt][1] = 0.f;
            csq[nt][0]  = csq[nt][1]  = 0.f;
        }
    }
#pragma unroll
    for (int nt = 0; nt < 8; nt++) {
        int col0 = nBase + nt * 8 + 2 * q;
        float b0 = bias[col0], b1 = bias[col0 + 1];
#pragma unroll
        for (int mt = 0; mt < 2; mt++) {
#pragma unroll
            for (int half = 0; half < 2; half++) {
                int r = base_row + mBase + mt * 16 + grp + half * 8;
                if (r < M) {
                    float v0 = acc[mt][nt][2*half + 0] + b0;
                    float v1 = acc[mt][nt][2*half + 1] + b1;
                    if (POST_RELU) { v0 = fmaxf(v0, 0.f); v1 = fmaxf(v1, 0.f); }
                    *(float2*)(out + (size_t)r * 128 + col0) =
                        make_float2(v0, v1);
                    if (STATS) {
                        csum[nt][0] += v0;      csum[nt][1] += v1;
                        csq[nt][0]  += v0 * v0; csq[nt][1]  += v1 * v1;
                    }
                }
            }
        }
    }

    if (STATS) {
        __syncthreads();
        float* ssum = (float*)Ahi;
        float* ssq  = ssum + 128;
        ssum[tid] = 0.f;                 // 256 threads zero both arrays
        __syncthreads();
#pragma unroll
        for (int nt = 0; nt < 8; nt++) {
            int col0 = nBase + nt * 8 + 2 * q;
            atomicAdd(&ssum[col0],     csum[nt][0]);
            atomicAdd(&ssum[col0 + 1], csum[nt][1]);
            atomicAdd(&ssq[col0],      csq[nt][0]);
            atomicAdd(&ssq[col0 + 1],  csq[nt][1]);
        }
        __syncthreads();
        if (tid < 128) {
            atomicAdd(&stats[tid],       ssum[tid]);
            atomicAdd(&stats[128 + tid], ssq[tid]);
        }
    }
}

__global__ void zero_pool_kernel(float4* __restrict__ pool) {
    int i = blockIdx.x * blockDim.x + threadIdx.x;
    pool[i] = make_float4(0.f, 0.f, 0.f, 0.f);
}

__global__ void pool_scatter_kernel(const float4* __restrict__ x,
                                    float4* __restrict__ pool,
                                    const int* __restrict__ batch,
                                    int N) {
    int n = blockIdx.x * 8 + (threadIdx.x >> 5);
    if (n >= N) return;
    int lane = threadIdx.x & 31;
    int g = batch[n];
    float4 v = x[(size_t)n * 32 + lane];
    red_add_f4(&pool[(size_t)g * 32 + lane], v);
}

__global__ void head2_kernel(const float* __restrict__ Hh,
                             const float* __restrict__ W,
                             const float* __restrict__ b,
                             float* __restrict__ out) {
    __shared__ float row[128];
    int g = blockIdx.x;
    int c = threadIdx.x;
    row[c]      = Hh[(size_t)g * 128 + c];
    row[c + 64] = Hh[(size_t)g * 128 + 64 + c];
    __syncthreads();
    float acc = b[c];
#pragma unroll 8
    for (int k = 0; k < 128; k++) acc = fmaf(row[k], W[k * 64 + c], acc);
    out[(size_t)g * 64 + c] = acc;
}

// ---------------- launcher ----------------
extern "C" void kernel_launch(void* const* d_in, const int* in_sizes, int n_in,
                              void* d_out, int out_size) {
    const float* x    = (const float*)d_in[0];
    const float* cW1  = (const float*)d_in[1];
    const float* cb1  = (const float*)d_in[2];
    const float* cgam = (const float*)d_in[3];
    const float* cbet = (const float*)d_in[4];
    const float* cW2  = (const float*)d_in[5];
    const float* cb2  = (const float*)d_in[6];
    const float* hW1  = (const float*)d_in[7];
    const float* hb1  = (const float*)d_in[8];
    const float* hW2  = (const float*)d_in[9];
    const float* hb2  = (const float*)d_in[10];
    const int* ei    = (const int*)d_in[11];   // [2, E] int32
    const int* batch = (const int*)d_in[12];   // [N]    int32
    float* out = (float*)d_out;

    float *bufX, *bufA, *bufB, *pool, *head, *stats;
    int *deg, *rowptr, *cursor, *csr;
    cudaGetSymbolAddress((void**)&bufX,   g_bufX);
    cudaGetSymbolAddress((void**)&bufA,   g_bufA);
    cudaGetSymbolAddress((void**)&bufB,   g_bufB);
    cudaGetSymbolAddress((void**)&pool,   g_pool);
    cudaGetSymbolAddress((void**)&head,   g_head);
    cudaGetSymbolAddress((void**)&stats,  g_stats);
    cudaGetSymbolAddress((void**)&deg,    g_deg);
    cudaGetSymbolAddress((void**)&rowptr, g_rowptr);
    cudaGetSymbolAddress((void**)&cursor, g_cursor);
    cudaGetSymbolAddress((void**)&csr,    g_csr);

    cudaFuncSetAttribute(gemm_k128<false, false, true>,
                         cudaFuncAttributeMaxDynamicSharedMemorySize,
                         GEMM_SMEM_BYTES);
    cudaFuncSetAttribute(gemm_k128<true, true, false>,
                         cudaFuncAttributeMaxDynamicSharedMemorySize,
                         GEMM_SMEM_BYTES);
    cudaFuncSetAttribute(gemm_k128<false, true, false>,
                         cudaFuncAttributeMaxDynamicSharedMemorySize,
                         GEMM_SMEM_BYTES);

    const int* e_src = ei;
    const int* e_dst = ei + EE;
    const int gemm_blocks = (NN + 127) / 128;  // 391

    // CSR build; launch index 3 = first gather (profiler capture slot)
    hist_kernel<<<(EE + 255) / 256, 256>>>(e_dst, deg);
    scan_kernel<<<1, 1024>>>(deg, rowptr, cursor);
    fill_kernel<<<(EE + 255) / 256, 256>>>(e_src, e_dst, cursor, csr);

    for (int l = 0; l < 3; l++) {
        const float* in = (l == 0) ? x : bufX;
        gather_kernel<<<(NN + 7) / 8, 256>>>(
            (const float4*)in, (float4*)bufA, rowptr, csr, stats);
        gemm_k128<false, false, true><<<gemm_blocks, 256, GEMM_SMEM_BYTES>>>(
            bufA, cW1 + l * HDIM * HDIM, cb1 + l * HDIM,
            nullptr, nullptr, bufB, stats, NN, 0.f);
        gemm_k128<true, true, false><<<gemm_blocks, 256, GEMM_SMEM_BYTES>>>(
            bufB, cW2 + l * HDIM * HDIM, cb2 + l * HDIM,
            cgam + l * HDIM, cbet + l * HDIM, bufX, stats, NN, 1.0f / NN);
    }

    zero_pool_kernel<<<64, 256>>>((float4*)pool);
    pool_scatter_kernel<<<(NN + 7) / 8, 256>>>(
        (const float4*)bufX, (float4*)pool, batch, NN);
    gemm_k128<false, true, false><<<(GG + 127) / 128, 256, GEMM_SMEM_BYTES>>>(
        pool, hW1, hb1, nullptr, nullptr, head, nullptr, GG, 0.f);
    head2_kernel<<<GG, 64>>>(head, hW2, hb2, out);
}

// round 13
// speedup vs baseline: 1.1937x; 1.1937x over previous
#include <cuda_runtime.h>
#include <cuda_bf16.h>
#include <cstddef>

#define NN   50000
#define EE   800000
#define HDIM 128
#define GG   512
#define OUTD 64
#define BN_EPS 1e-5f

// ---------------- device scratch (no allocation allowed) ----------------
__device__ __align__(16) float g_bufX[NN * HDIM];
__device__ __align__(16) float g_bufA[NN * HDIM];
__device__ __align__(16) float g_bufB[NN * HDIM];
__device__ __align__(16) float g_pool[GG * HDIM];
__device__ __align__(16) float g_head[GG * HDIM];
__device__ __align__(16) float g_stats[2 * HDIM];
__device__ __align__(16) float g_scaleK[HDIM];
__device__ __align__(16) float g_shiftK[HDIM];
// CSR scratch (deg zero at load; scan_kernel re-zeroes after use)
__device__ __align__(16) int g_deg[NN];
__device__ __align__(16) int g_rowptr[NN + 4];
__device__ __align__(16) int g_cursor[NN];
__device__ int g_csr[EE];

// ---------------- helpers ----------------
__device__ __forceinline__ void red_add_f4(float4* addr, float4 v) {
    asm volatile("red.global.add.v4.f32 [%0], {%1,%2,%3,%4};"
                 :: "l"(addr), "f"(v.x), "f"(v.y), "f"(v.z), "f"(v.w)
                 : "memory");
}

__device__ __forceinline__ void cp_async16(void* smem_dst, const void* gsrc) {
    unsigned d = (unsigned)__cvta_generic_to_shared(smem_dst);
    asm volatile("cp.async.cg.shared.global [%0], [%1], 16;"
                 :: "r"(d), "l"(gsrc));
}
#define CP_COMMIT()  asm volatile("cp.async.commit_group;")
#define CP_WAIT0()   asm volatile("cp.async.wait_group 0;")

// bf16 mma: D(16x8,f32) += A(16x16,bf16 row) * B(16x8,bf16 col)
__device__ __forceinline__ void mma_bf16(float* d, const unsigned* a,
                                         const unsigned* b) {
    asm volatile(
        "mma.sync.aligned.m16n8k16.row.col.f32.bf16.bf16.f32 "
        "{%0,%1,%2,%3}, {%4,%5,%6,%7}, {%8,%9}, {%0,%1,%2,%3};"
        : "+f"(d[0]), "+f"(d[1]), "+f"(d[2]), "+f"(d[3])
        : "r"(a[0]), "r"(a[1]), "r"(a[2]), "r"(a[3]), "r"(b[0]), "r"(b[1]));
}

__device__ __forceinline__ unsigned pack_bf16x2(__nv_bfloat16 a, __nv_bfloat16 b) {
    return ((unsigned)__bfloat16_as_ushort(b) << 16) |
           (unsigned)__bfloat16_as_ushort(a);
}

__device__ __forceinline__ void split_bf16(float v, __nv_bfloat16& hi,
                                           __nv_bfloat16& lo) {
    hi = __float2bfloat16_rn(v);
    lo = __float2bfloat16_rn(v - __bfloat162float(hi));
}

// ---------------- CSR build kernels ----------------
__global__ void hist_kernel(const int* __restrict__ dst, int* __restrict__ deg) {
    int e = blockIdx.x * blockDim.x + threadIdx.x;
    if (e < EE) atomicAdd(&deg[dst[e]], 1);
}

// single-block exclusive scan of deg -> rowptr+cursor, int4-vectorized;
// zeroes deg after use (so hist finds it clean on the next call)
__global__ void scan_kernel(int4* __restrict__ deg4,
                            int* __restrict__ rowptr,
                            int* __restrict__ cursor) {
    __shared__ int ssum[1024];
    const int T = 1024, CH4 = 13;          // 13 int4 = 52 ints per thread
    const int n4 = NN / 4;                  // 12500
    int t = threadIdx.x;
    int b4 = t * CH4;
    int e4 = b4 + CH4; if (e4 > n4) e4 = n4;
    int s = 0;
    for (int i = b4; i < e4; i++) {
        int4 v = deg4[i];
        s += v.x + v.y + v.z + v.w;
    }
    ssum[t] = s;
    __syncthreads();
    for (int off = 1; off < T; off <<= 1) {
        int v = (t >= off) ? ssum[t - off] : 0;
        __syncthreads();
        ssum[t] += v;
        __syncthreads();
    }
    int run = (t == 0) ? 0 : ssum[t - 1];
    int4* rp4 = (int4*)rowptr;
    int4* cu4 = (int4*)cursor;
    for (int i = b4; i < e4; i++) {
        int4 v = deg4[i];
        int4 r;
        r.x = run; run += v.x;
        r.y = run; run += v.y;
        r.z = run; run += v.z;
        r.w = run; run += v.w;
        rp4[i] = r;
        cu4[i] = r;
        deg4[i] = make_int4(0, 0, 0, 0);
    }
    if (t == T - 1) rowptr[NN] = ssum[T - 1];
}

__global__ void fill_kernel(const int* __restrict__ src,
                            const int* __restrict__ dst,
                            int* __restrict__ cursor,
                            int* __restrict__ csr) {
    int e = blockIdx.x * blockDim.x + threadIdx.x;
    if (e >= EE) return;
    int pos = atomicAdd(&cursor[dst[e]], 1);
    csr[pos] = src[e];
}

// ---------------- aggregation: warp per node, gather over CSR ----------------
__global__ void gather_kernel(const float4* __restrict__ x,
                              float4* __restrict__ agg,
                              const int* __restrict__ rowptr,
                              const int* __restrict__ csr,
                              float* __restrict__ stats) {
    if (blockIdx.x == 0 && threadIdx.x < 2 * HDIM) stats[threadIdx.x] = 0.f;
    int n = blockIdx.x * 8 + (threadIdx.x >> 5);
    if (n >= NN) return;
    int lane = threadIdx.x & 31;
    int b = rowptr[n], e = rowptr[n + 1];
    float4 a0 = x[(size_t)n * 32 + lane];
    float4 a1 = make_float4(0.f, 0.f, 0.f, 0.f);
    float4 a2 = make_float4(0.f, 0.f, 0.f, 0.f);
    float4 a3 = make_float4(0.f, 0.f, 0.f, 0.f);
    int i = b;
    for (; i + 4 <= e; i += 4) {
        int s0 = csr[i], s1 = csr[i + 1], s2 = csr[i + 2], s3 = csr[i + 3];
        float4 v0 = x[(size_t)s0 * 32 + lane];
        float4 v1 = x[(size_t)s1 * 32 + lane];
        float4 v2 = x[(size_t)s2 * 32 + lane];
        float4 v3 = x[(size_t)s3 * 32 + lane];
        a0.x += v0.x; a0.y += v0.y; a0.z += v0.z; a0.w += v0.w;
        a1.x += v1.x; a1.y += v1.y; a1.z += v1.z; a1.w += v1.w;
        a2.x += v2.x; a2.y += v2.y; a2.z += v2.z; a2.w += v2.w;
        a3.x += v3.x; a3.y += v3.y; a3.z += v3.z; a3.w += v3.w;
    }
    for (; i < e; i++) {
        float4 v = x[(size_t)csr[i] * 32 + lane];
        a0.x += v.x; a0.y += v.y; a0.z += v.z; a0.w += v.w;
    }
    a0.x += a1.x + a2.x + a3.x;
    a0.y += a1.y + a2.y + a3.y;
    a0.z += a1.z + a2.z + a3.z;
    a0.w += a1.w + a2.w + a3.w;
    agg[(size_t)n * 32 + lane] = a0;
}

// ---------------- GEMM: bf16x3 split-precision tensor-core MMA ----------
// (byte-identical to the R6 kernel that measured 506 us)
#define GEMM_SMEM_BYTES 49152

template <bool PRE_BN, bool POST_RELU, bool STATS>
__global__ void __launch_bounds__(256, 2)
gemm_k128(const float* __restrict__ A, const float* __restrict__ W,
          const float* __restrict__ bias, const float* __restrict__ scaleK,
          const float* __restrict__ shiftK, float* __restrict__ out,
          float* __restrict__ stats, int M) {
    extern __shared__ char smem[];
    float*          stageA = (float*)smem;                 // [2][128][16]
    float*          Wraw   = (float*)(smem + 16384);       // [2][16][128]
    __nv_bfloat16*  Ahi    = (__nv_bfloat16*)(smem + 32768);
    __nv_bfloat16*  Alo    = (__nv_bfloat16*)(smem + 36864);
    __nv_bfloat16*  Wthi   = (__nv_bfloat16*)(smem + 40960);
    __nv_bfloat16*  Wtlo   = (__nv_bfloat16*)(smem + 45056);

    const int tid  = threadIdx.x;
    const int w    = tid >> 5;
    const int lane = tid & 31;
    const int grp  = lane >> 2;
    const int q    = lane & 3;
    const int mBase = (w & 3) * 32;
    const int nBase = (w >> 2) * 64;
    const int base_row = blockIdx.x * 128;

    float acc[2][8][4];
#pragma unroll
    for (int mt = 0; mt < 2; mt++)
#pragma unroll
        for (int nt = 0; nt < 8; nt++)
#pragma unroll
            for (int c = 0; c < 4; c++) acc[mt][nt][c] = 0.f;

    auto issue_tile = [&](int buf, int kb) {
#pragma unroll
        for (int t = 0; t < 2; t++) {
            int idx = tid + t * 256;
            int row = idx >> 2, j = idx & 3;
            int gr  = base_row + row;
            int cgr = gr < M ? gr : 0;
            cp_async16(stageA + buf * 2048 + row * 16 + 4 * j,
                       A + (size_t)cgr * 128 + kb + 4 * j);
        }
#pragma unroll
        for (int t = 0; t < 2; t++) {
            int idx = tid + t * 256;
            int kk = idx >> 5, c = idx & 31;
            cp_async16(Wraw + buf * 2048 + kk * 128 + 4 * c,
                       W + (size_t)(kb + kk) * 128 + 4 * c);
        }
        CP_COMMIT();
    };

    issue_tile(0, 0);

    for (int kb8 = 0; kb8 < 8; kb8++) {
        const int buf = kb8 & 1;
        CP_WAIT0();
        __syncthreads();
        if (kb8 < 7) issue_tile(buf ^ 1, (kb8 + 1) * 16);

#pragma unroll
        for (int t = 0; t < 2; t++) {
            int idx = tid + t * 256;
            int row = idx >> 2, j = idx & 3;
            float4 v = *(const float4*)(stageA + buf * 2048 + row * 16 + 4 * j);
            if (PRE_BN) {
                int k = kb8 * 16 + 4 * j;
                float4 sc = *(const float4*)(scaleK + k);
                float4 sh = *(const float4*)(shiftK + k);
                v.x = fmaxf(fmaf(v.x, sc.x, sh.x), 0.f);
                v.y = fmaxf(fmaf(v.y, sc.y, sh.y), 0.f);
                v.z = fmaxf(fmaf(v.z, sc.z, sh.z), 0.f);
                v.w = fmaxf(fmaf(v.w, sc.w, sh.w), 0.f);
            }
            __nv_bfloat16 hx,lx,hy,ly,hz,lz,hw,lw;
            split_bf16(v.x,hx,lx); split_bf16(v.y,hy,ly);
            split_bf16(v.z,hz,lz); split_bf16(v.w,hw,lw);
            *(uint2*)(Ahi + row*16 + 4*j) =
                make_uint2(pack_bf16x2(hx,hy), pack_bf16x2(hz,hw));
            *(uint2*)(Alo + row*16 + 4*j) =
                make_uint2(pack_bf16x2(lx,ly), pack_bf16x2(lz,lw));
        }
#pragma unroll
        for (int t = 0; t < 2; t++) {
            int idx = tid + t * 256;
            int c = idx & 127, jk = idx >> 7;
            float v0 = Wraw[buf * 2048 + (4*jk+0) * 128 + c];
            float v1 = Wraw[buf * 2048 + (4*jk+1) * 128 + c];
            float v2 = Wraw[buf * 2048 + (4*jk+2) * 128 + c];
            float v3 = Wraw[buf * 2048 + (4*jk+3) * 128 + c];
            __nv_bfloat16 h0,l0,h1,l1,h2,l2,h3,l3;
            split_bf16(v0,h0,l0); split_bf16(v1,h1,l1);
            split_bf16(v2,h2,l2); split_bf16(v3,h3,l3);
            *(uint2*)(Wthi + c*16 + 4*jk) =
                make_uint2(pack_bf16x2(h0,h1), pack_bf16x2(h2,h3));
            *(uint2*)(Wtlo + c*16 + 4*jk) =
                make_uint2(pack_bf16x2(l0,l1), pack_bf16x2(l2,l3));
        }
        __syncthreads();

        unsigned ah[2][4], al[2][4];
#pragma unroll
        for (int mt = 0; mt < 2; mt++) {
            int r = mBase + mt * 16 + grp;
            ah[mt][0] = *(const unsigned*)(Ahi + r*16 + 2*q);
            ah[mt][1] = *(const unsigned*)(Ahi + (r+8)*16 + 2*q);
            ah[mt][2] = *(const unsigned*)(Ahi + r*16 + 2*q + 8);
            ah[mt][3] = *(const unsigned*)(Ahi + (r+8)*16 + 2*q + 8);
            al[mt][0] = *(const unsigned*)(Alo + r*16 + 2*q);
            al[mt][1] = *(const unsigned*)(Alo + (r+8)*16 + 2*q);
            al[mt][2] = *(const unsigned*)(Alo + r*16 + 2*q + 8);
            al[mt][3] = *(const unsigned*)(Alo + (r+8)*16 + 2*q + 8);
        }
#pragma unroll
        for (int nt = 0; nt < 8; nt++) {
            int n = nBase + nt * 8 + grp;
            unsigned bh[2], bl[2];
            bh[0] = *(const unsigned*)(Wthi + n*16 + 2*q);
            bh[1] = *(const unsigned*)(Wthi + n*16 + 2*q + 8);
            bl[0] = *(const unsigned*)(Wtlo + n*16 + 2*q);
            bl[1] = *(const unsigned*)(Wtlo + n*16 + 2*q + 8);
#pragma unroll
            for (int mt = 0; mt < 2; mt++) {
                mma_bf16(acc[mt][nt], ah[mt], bh);
                mma_bf16(acc[mt][nt], ah[mt], bl);
                mma_bf16(acc[mt][nt], al[mt], bh);
            }
        }
    }

    float csum[8][2], csq[8][2];
    if (STATS) {
#pragma unroll
        for (int nt = 0; nt < 8; nt++) {
            csum[nt][0] = csum[nt][1] = 0.f;
            csq[nt][0]  = csq[nt][1]  = 0.f;
        }
    }
#pragma unroll
    for (int nt = 0; nt < 8; nt++) {
        int col0 = nBase + nt * 8 + 2 * q;
        float b0 = bias[col0], b1 = bias[col0 + 1];
#pragma unroll
        for (int mt = 0; mt < 2; mt++) {
#pragma unroll
            for (int half = 0; half < 2; half++) {
                int r = base_row + mBase + mt * 16 + grp + half * 8;
                if (r < M) {
                    float v0 = acc[mt][nt][2*half + 0] + b0;
                    float v1 = acc[mt][nt][2*half + 1] + b1;
                    if (POST_RELU) { v0 = fmaxf(v0, 0.f); v1 = fmaxf(v1, 0.f); }
                    *(float2*)(out + (size_t)r * 128 + col0) =
                        make_float2(v0, v1);
                    if (STATS) {
                        csum[nt][0] += v0;      csum[nt][1] += v1;
                        csq[nt][0]  += v0 * v0; csq[nt][1]  += v1 * v1;
                    }
                }
            }
        }
    }

    if (STATS) {
        __syncthreads();
        float* ssum = (float*)Ahi;
        float* ssq  = ssum + 128;
        ssum[tid] = 0.f;
        __syncthreads();
#pragma unroll
        for (int nt = 0; nt < 8; nt++) {
            int col0 = nBase + nt * 8 + 2 * q;
            atomicAdd(&ssum[col0],     csum[nt][0]);
            atomicAdd(&ssum[col0 + 1], csum[nt][1]);
            atomicAdd(&ssq[col0],      csq[nt][0]);
            atomicAdd(&ssq[col0 + 1],  csq[nt][1]);
        }
        __syncthreads();
        if (tid < 128) {
            atomicAdd(&stats[tid],       ssum[tid]);
            atomicAdd(&stats[128 + tid], ssq[tid]);
        }
    }
}

__global__ void bn_finalize_kernel(const float* __restrict__ stats,
                                   const float* __restrict__ gamma,
                                   const float* __restrict__ beta,
                                   float* __restrict__ scaleK,
                                   float* __restrict__ shiftK, float invM) {
    int c = threadIdx.x;
    float mu   = stats[c] * invM;
    float var  = stats[128 + c] * invM - mu * mu;
    float rstd = rsqrtf(var + BN_EPS);
    float sc   = gamma[c] * rstd;
    scaleK[c] = sc;
    shiftK[c] = beta[c] - mu * sc;
}

__global__ void zero_pool_kernel(float4* __restrict__ pool) {
    int i = blockIdx.x * blockDim.x + threadIdx.x;
    pool[i] = make_float4(0.f, 0.f, 0.f, 0.f);
}

__global__ void pool_scatter_kernel(const float4* __restrict__ x,
                                    float4* __restrict__ pool,
                                    const int* __restrict__ batch,
                                    int N) {
    int n = blockIdx.x * 8 + (threadIdx.x >> 5);
    if (n >= N) return;
    int lane = threadIdx.x & 31;
    int g = batch[n];
    float4 v = x[(size_t)n * 32 + lane];
    red_add_f4(&pool[(size_t)g * 32 + lane], v);
}

__global__ void head2_kernel(const float* __restrict__ Hh,
                             const float* __restrict__ W,
                             const float* __restrict__ b,
                             float* __restrict__ out) {
    __shared__ float row[128];
    int g = blockIdx.x;
    int c = threadIdx.x;
    row[c]      = Hh[(size_t)g * 128 + c];
    row[c + 64] = Hh[(size_t)g * 128 + 64 + c];
    __syncthreads();
    float acc = b[c];
#pragma unroll 8
    for (int k = 0; k < 128; k++) acc = fmaf(row[k], W[k * 64 + c], acc);
    out[(size_t)g * 64 + c] = acc;
}

// ---------------- launcher ----------------
extern "C" void kernel_launch(void* const* d_in, const int* in_sizes, int n_in,
                              void* d_out, int out_size) {
    const float* x    = (const float*)d_in[0];
    const float* cW1  = (const float*)d_in[1];
    const float* cb1  = (const float*)d_in[2];
    const float* cgam = (const float*)d_in[3];
    const float* cbet = (const float*)d_in[4];
    const float* cW2  = (const float*)d_in[5];
    const float* cb2  = (const float*)d_in[6];
    const float* hW1  = (const float*)d_in[7];
    const float* hb1  = (const float*)d_in[8];
    const float* hW2  = (const float*)d_in[9];
    const float* hb2  = (const float*)d_in[10];
    const int* ei    = (const int*)d_in[11];   // [2, E] int32
    const int* batch = (const int*)d_in[12];   // [N]    int32
    float* out = (float*)d_out;

    float *bufX, *bufA, *bufB, *pool, *head, *stats, *scaleK, *shiftK;
    int *deg, *rowptr, *cursor, *csr;
    cudaGetSymbolAddress((void**)&bufX,   g_bufX);
    cudaGetSymbolAddress((void**)&bufA,   g_bufA);
    cudaGetSymbolAddress((void**)&bufB,   g_bufB);
    cudaGetSymbolAddress((void**)&pool,   g_pool);
    cudaGetSymbolAddress((void**)&head,   g_head);
    cudaGetSymbolAddress((void**)&stats,  g_stats);
    cudaGetSymbolAddress((void**)&scaleK, g_scaleK);
    cudaGetSymbolAddress((void**)&shiftK, g_shiftK);
    cudaGetSymbolAddress((void**)&deg,    g_deg);
    cudaGetSymbolAddress((void**)&rowptr, g_rowptr);
    cudaGetSymbolAddress((void**)&cursor, g_cursor);
    cudaGetSymbolAddress((void**)&csr,    g_csr);

    cudaFuncSetAttribute(gemm_k128<false, false, true>,
                         cudaFuncAttributeMaxDynamicSharedMemorySize,
                         GEMM_SMEM_BYTES);
    cudaFuncSetAttribute(gemm_k128<true, true, false>,
                         cudaFuncAttributeMaxDynamicSharedMemorySize,
                         GEMM_SMEM_BYTES);
    cudaFuncSetAttribute(gemm_k128<false, true, false>,
                         cudaFuncAttributeMaxDynamicSharedMemorySize,
                         GEMM_SMEM_BYTES);

    const int* e_src = ei;
    const int* e_dst = ei + EE;
    const int gemm_blocks = (NN + 127) / 128;  // 391

    // CSR build (deg arrives zeroed; scan re-zeroes it for the next call)
    hist_kernel<<<(EE + 255) / 256, 256>>>(e_dst, deg);
    scan_kernel<<<1, 1024>>>((int4*)deg, rowptr, cursor);
    fill_kernel<<<(EE + 255) / 256, 256>>>(e_src, e_dst, cursor, csr);

    for (int l = 0; l < 3; l++) {
        const float* in = (l == 0) ? x : bufX;
        gather_kernel<<<(NN + 7) / 8, 256>>>(
            (const float4*)in, (float4*)bufA, rowptr, csr, stats);
        gemm_k128<false, false, true><<<gemm_blocks, 256, GEMM_SMEM_BYTES>>>(
            bufA, cW1 + l * HDIM * HDIM, cb1 + l * HDIM,
            nullptr, nullptr, bufB, stats, NN);
        bn_finalize_kernel<<<1, 128>>>(stats, cgam + l * HDIM, cbet + l * HDIM,
                                       scaleK, shiftK, 1.0f / NN);
        gemm_k128<true, true, false><<<gemm_blocks, 256, GEMM_SMEM_BYTES>>>(
            bufB, cW2 + l * HDIM * HDIM, cb2 + l * HDIM,
            scaleK, shiftK, bufX, nullptr, NN);
    }

    zero_pool_kernel<<<64, 256>>>((float4*)pool);
    pool_scatter_kernel<<<(NN + 7) / 8, 256>>>(
        (const float4*)bufX, (float4*)pool, batch, NN);
    gemm_k128<false, true, false><<<(GG + 127) / 128, 256, GEMM_SMEM_BYTES>>>(
        pool, hW1, hb1, nullptr, nullptr, head, nullptr, GG);
    head2_kernel<<<GG, 64>>>(head, hW2, hb2, out);
}

// round 15
// speedup vs baseline: 1.1972x; 1.0030x over previous
#include <cuda_runtime.h>
#include <cuda_bf16.h>
#include <cstddef>

#define NN   50000
#define EE   800000
#define HDIM 128
#define GG   512
#define OUTD 64
#define BN_EPS 1e-5f

// ---------------- device scratch (no allocation allowed) ----------------
__device__ __align__(16) float g_bufX[NN * HDIM];
__device__ __align__(16) float g_bufA[NN * HDIM];
__device__ __align__(16) float g_bufB[NN * HDIM];
__device__ __align__(16) float g_pool[GG * HDIM];
__device__ __align__(16) float g_head[GG * HDIM];
__device__ __align__(16) float g_stats[2 * HDIM];
// CSR scratch (deg zero at load; scan_kernel re-zeroes after use)
__device__ __align__(16) int g_deg[NN];
__device__ __align__(16) int g_rowptr[NN + 4];
__device__ __align__(16) int g_cursor[NN];
__device__ int g_csr[EE];

// ---------------- helpers ----------------
__device__ __forceinline__ void red_add_f4(float4* addr, float4 v) {
    asm volatile("red.global.add.v4.f32 [%0], {%1,%2,%3,%4};"
                 :: "l"(addr), "f"(v.x), "f"(v.y), "f"(v.z), "f"(v.w)
                 : "memory");
}

__device__ __forceinline__ void cp_async16(void* smem_dst, const void* gsrc) {
    unsigned d = (unsigned)__cvta_generic_to_shared(smem_dst);
    asm volatile("cp.async.cg.shared.global [%0], [%1], 16;"
                 :: "r"(d), "l"(gsrc));
}
#define CP_COMMIT()  asm volatile("cp.async.commit_group;")
#define CP_WAIT0()   asm volatile("cp.async.wait_group 0;")

// bf16 mma: D(16x8,f32) += A(16x16,bf16 row) * B(16x8,bf16 col)
__device__ __forceinline__ void mma_bf16(float* d, const unsigned* a,
                                         const unsigned* b) {
    asm volatile(
        "mma.sync.aligned.m16n8k16.row.col.f32.bf16.bf16.f32 "
        "{%0,%1,%2,%3}, {%4,%5,%6,%7}, {%8,%9}, {%0,%1,%2,%3};"
        : "+f"(d[0]), "+f"(d[1]), "+f"(d[2]), "+f"(d[3])
        : "r"(a[0]), "r"(a[1]), "r"(a[2]), "r"(a[3]), "r"(b[0]), "r"(b[1]));
}

__device__ __forceinline__ unsigned pack_bf16x2(__nv_bfloat16 a, __nv_bfloat16 b) {
    return ((unsigned)__bfloat16_as_ushort(b) << 16) |
           (unsigned)__bfloat16_as_ushort(a);
}

__device__ __forceinline__ void split_bf16(float v, __nv_bfloat16& hi,
                                           __nv_bfloat16& lo) {
    hi = __float2bfloat16_rn(v);
    lo = __float2bfloat16_rn(v - __bfloat162float(hi));
}

// ---------------- CSR build kernels (int4-vectorized, 4 edges/thread) -----
__global__ void hist_kernel(const int4* __restrict__ dst4,
                            int* __restrict__ deg) {
    int i = blockIdx.x * blockDim.x + threadIdx.x;   // EE/4 = 200000 threads
    if (i >= EE / 4) return;
    int4 d = dst4[i];
    atomicAdd(&deg[d.x], 1);
    atomicAdd(&deg[d.y], 1);
    atomicAdd(&deg[d.z], 1);
    atomicAdd(&deg[d.w], 1);
}

// single-block exclusive scan of deg -> rowptr+cursor, int4-vectorized;
// zeroes deg after use (so hist finds it clean on the next call)
__global__ void scan_kernel(int4* __restrict__ deg4,
                            int* __restrict__ rowptr,
                            int* __restrict__ cursor) {
    __shared__ int ssum[1024];
    const int T = 1024, CH4 = 13;          // 13 int4 = 52 ints per thread
    const int n4 = NN / 4;                  // 12500
    int t = threadIdx.x;
    int b4 = t * CH4;
    int e4 = b4 + CH4; if (e4 > n4) e4 = n4;
    int s = 0;
    for (int i = b4; i < e4; i++) {
        int4 v = deg4[i];
        s += v.x + v.y + v.z + v.w;
    }
    ssum[t] = s;
    __syncthreads();
    for (int off = 1; off < T; off <<= 1) {
        int v = (t >= off) ? ssum[t - off] : 0;
        __syncthreads();
        ssum[t] += v;
        __syncthreads();
    }
    int run = (t == 0) ? 0 : ssum[t - 1];
    int4* rp4 = (int4*)rowptr;
    int4* cu4 = (int4*)cursor;
    for (int i = b4; i < e4; i++) {
        int4 v = deg4[i];
        int4 r;
        r.x = run; run += v.x;
        r.y = run; run += v.y;
        r.z = run; run += v.z;
        r.w = run; run += v.w;
        rp4[i] = r;
        cu4[i] = r;
        deg4[i] = make_int4(0, 0, 0, 0);
    }
    if (t == T - 1) rowptr[NN] = ssum[T - 1];
}

__global__ void fill_kernel(const int4* __restrict__ src4,
                            const int4* __restrict__ dst4,
                            int* __restrict__ cursor,
                            int* __restrict__ csr) {
    int i = blockIdx.x * blockDim.x + threadIdx.x;
    if (i >= EE / 4) return;
    int4 s = src4[i];
    int4 d = dst4[i];
    csr[atomicAdd(&cursor[d.x], 1)] = s.x;
    csr[atomicAdd(&cursor[d.y], 1)] = s.y;
    csr[atomicAdd(&cursor[d.z], 1)] = s.z;
    csr[atomicAdd(&cursor[d.w], 1)] = s.w;
}

// ---------------- aggregation: warp per node, gather over CSR ----------------
__global__ void gather_kernel(const float4* __restrict__ x,
                              float4* __restrict__ agg,
                              const int* __restrict__ rowptr,
                              const int* __restrict__ csr,
                              float* __restrict__ stats) {
    if (blockIdx.x == 0 && threadIdx.x < 2 * HDIM) stats[threadIdx.x] = 0.f;
    int n = blockIdx.x * 8 + (threadIdx.x >> 5);
    if (n >= NN) return;
    int lane = threadIdx.x & 31;
    int b = rowptr[n], e = rowptr[n + 1];
    float4 a0 = x[(size_t)n * 32 + lane];
    float4 a1 = make_float4(0.f, 0.f, 0.f, 0.f);
    float4 a2 = make_float4(0.f, 0.f, 0.f, 0.f);
    float4 a3 = make_float4(0.f, 0.f, 0.f, 0.f);
    int i = b;
    for (; i + 4 <= e; i += 4) {
        int s0 = csr[i], s1 = csr[i + 1], s2 = csr[i + 2], s3 = csr[i + 3];
        float4 v0 = x[(size_t)s0 * 32 + lane];
        float4 v1 = x[(size_t)s1 * 32 + lane];
        float4 v2 = x[(size_t)s2 * 32 + lane];
        float4 v3 = x[(size_t)s3 * 32 + lane];
        a0.x += v0.x; a0.y += v0.y; a0.z += v0.z; a0.w += v0.w;
        a1.x += v1.x; a1.y += v1.y; a1.z += v1.z; a1.w += v1.w;
        a2.x += v2.x; a2.y += v2.y; a2.z += v2.z; a2.w += v2.w;
        a3.x += v3.x; a3.y += v3.y; a3.z += v3.z; a3.w += v3.w;
    }
    for (; i < e; i++) {
        float4 v = x[(size_t)csr[i] * 32 + lane];
        a0.x += v.x; a0.y += v.y; a0.z += v.z; a0.w += v.w;
    }
    a0.x += a1.x + a2.x + a3.x;
    a0.y += a1.y + a2.y + a3.y;
    a0.z += a1.z + a2.z + a3.z;
    a0.w += a1.w + a2.w + a3.w;
    agg[(size_t)n * 32 + lane] = a0;
}

// ---------------- GEMM: bf16x3 split-precision tensor-core MMA ----------
// PRE_BN: derive scale/shift from stats/gamma/beta in-block (BN fold).
#define GEMM_SMEM_BYTES 50176

template <bool PRE_BN, bool POST_RELU, bool STATS>
__global__ void __launch_bounds__(256, 2)
gemm_k128(const float* __restrict__ A, const float* __restrict__ W,
          const float* __restrict__ bias, const float* __restrict__ gamma,
          const float* __restrict__ beta, float* __restrict__ out,
          float* __restrict__ stats, int M, float invM) {
    extern __shared__ char smem[];
    float*          stageA = (float*)smem;                 // [2][128][16]
    float*          Wraw   = (float*)(smem + 16384);       // [2][16][128]
    __nv_bfloat16*  Ahi    = (__nv_bfloat16*)(smem + 32768);
    __nv_bfloat16*  Alo    = (__nv_bfloat16*)(smem + 36864);
    __nv_bfloat16*  Wthi   = (__nv_bfloat16*)(smem + 40960);
    __nv_bfloat16*  Wtlo   = (__nv_bfloat16*)(smem + 45056);
    float*          s_scale = (float*)(smem + 49152);      // [128]
    float*          s_shift = (float*)(smem + 49664);      // [128]

    const int tid  = threadIdx.x;
    const int w    = tid >> 5;
    const int lane = tid & 31;
    const int grp  = lane >> 2;
    const int q    = lane & 3;
    const int mBase = (w & 3) * 32;
    const int nBase = (w >> 2) * 64;
    const int base_row = blockIdx.x * 128;

    if (PRE_BN && tid < 128) {
        float mu   = stats[tid] * invM;
        float var  = stats[128 + tid] * invM - mu * mu;
        float rstd = rsqrtf(var + BN_EPS);
        float sc   = gamma[tid] * rstd;
        s_scale[tid] = sc;
        s_shift[tid] = beta[tid] - mu * sc;
    }

    float acc[2][8][4];
#pragma unroll
    for (int mt = 0; mt < 2; mt++)
#pragma unroll
        for (int nt = 0; nt < 8; nt++)
#pragma unroll
            for (int c = 0; c < 4; c++) acc[mt][nt][c] = 0.f;

    auto issue_tile = [&](int buf, int kb) {
#pragma unroll
        for (int t = 0; t < 2; t++) {
            int idx = tid + t * 256;
            int row = idx >> 2, j = idx & 3;
            int gr  = base_row + row;
            int cgr = gr < M ? gr : 0;
            cp_async16(stageA + buf * 2048 + row * 16 + 4 * j,
                       A + (size_t)cgr * 128 + kb + 4 * j);
        }
#pragma unroll
        for (int t = 0; t < 2; t++) {
            int idx = tid + t * 256;
            int kk = idx >> 5, c = idx & 31;
            cp_async16(Wraw + buf * 2048 + kk * 128 + 4 * c,
                       W + (size_t)(kb + kk) * 128 + 4 * c);
        }
        CP_COMMIT();
    };

    issue_tile(0, 0);

    for (int kb8 = 0; kb8 < 8; kb8++) {
        const int buf = kb8 & 1;
        CP_WAIT0();
        __syncthreads();
        if (kb8 < 7) issue_tile(buf ^ 1, (kb8 + 1) * 16);

#pragma unroll
        for (int t = 0; t < 2; t++) {
            int idx = tid + t * 256;
            int row = idx >> 2, j = idx & 3;
            float4 v = *(const float4*)(stageA + buf * 2048 + row * 16 + 4 * j);
            if (PRE_BN) {
                int k = kb8 * 16 + 4 * j;
                v.x = fmaxf(fmaf(v.x, s_scale[k + 0], s_shift[k + 0]), 0.f);
                v.y = fmaxf(fmaf(v.y, s_scale[k + 1], s_shift[k + 1]), 0.f);
                v.z = fmaxf(fmaf(v.z, s_scale[k + 2], s_shift[k + 2]), 0.f);
                v.w = fmaxf(fmaf(v.w, s_scale[k + 3], s_shift[k + 3]), 0.f);
            }
            __nv_bfloat16 hx,lx,hy,ly,hz,lz,hw,lw;
            split_bf16(v.x,hx,lx); split_bf16(v.y,hy,ly);
            split_bf16(v.z,hz,lz); split_bf16(v.w,hw,lw);
            *(uint2*)(Ahi + row*16 + 4*j) =
                make_uint2(pack_bf16x2(hx,hy), pack_bf16x2(hz,hw));
            *(uint2*)(Alo + row*16 + 4*j) =
                make_uint2(pack_bf16x2(lx,ly), pack_bf16x2(lz,lw));
        }
#pragma unroll
        for (int t = 0; t < 2; t++) {
            int idx = tid + t * 256;
            int c = idx & 127, jk = idx >> 7;
            float v0 = Wraw[buf * 2048 + (4*jk+0) * 128 + c];
            float v1 = Wraw[buf * 2048 + (4*jk+1) * 128 + c];
            float v2 = Wraw[buf * 2048 + (4*jk+2) * 128 + c];
            float v3 = Wraw[buf * 2048 + (4*jk+3) * 128 + c];
            __nv_bfloat16 h0,l0,h1,l1,h2,l2,h3,l3;
            split_bf16(v0,h0,l0); split_bf16(v1,h1,l1);
            split_bf16(v2,h2,l2); split_bf16(v3,h3,l3);
            *(uint2*)(Wthi + c*16 + 4*jk) =
                make_uint2(pack_bf16x2(h0,h1), pack_bf16x2(h2,h3));
            *(uint2*)(Wtlo + c*16 + 4*jk) =
                make_uint2(pack_bf16x2(l0,l1), pack_bf16x2(l2,l3));
        }
        __syncthreads();

        unsigned ah[2][4], al[2][4];
#pragma unroll
        for (int mt = 0; mt < 2; mt++) {
            int r = mBase + mt * 16 + grp;
            ah[mt][0] = *(const unsigned*)(Ahi + r*16 + 2*q);
            ah[mt][1] = *(const unsigned*)(Ahi + (r+8)*16 + 2*q);
            ah[mt][2] = *(const unsigned*)(Ahi + r*16 + 2*q + 8);
            ah[mt][3] = *(const unsigned*)(Ahi + (r+8)*16 + 2*q + 8);
            al[mt][0] = *(const unsigned*)(Alo + r*16 + 2*q);
            al[mt][1] = *(const unsigned*)(Alo + (r+8)*16 + 2*q);
            al[mt][2] = *(const unsigned*)(Alo + r*16 + 2*q + 8);
            al[mt][3] = *(const unsigned*)(Alo + (r+8)*16 + 2*q + 8);
        }
#pragma unroll
        for (int nt = 0; nt < 8; nt++) {
            int n = nBase + nt * 8 + grp;
            unsigned bh[2], bl[2];
            bh[0] = *(const unsigned*)(Wthi + n*16 + 2*q);
            bh[1] = *(const unsigned*)(Wthi + n*16 + 2*q + 8);
            bl[0] = *(const unsigned*)(Wtlo + n*16 + 2*q);
            bl[1] = *(const unsigned*)(Wtlo + n*16 + 2*q + 8);
#pragma unroll
            for (int mt = 0; mt < 2; mt++) {
                mma_bf16(acc[mt][nt], ah[mt], bh);
                mma_bf16(acc[mt][nt], ah[mt], bl);
                mma_bf16(acc[mt][nt], al[mt], bh);
            }
        }
    }

    float csum[8][2], csq[8][2];
    if (STATS) {
#pragma unroll
        for (int nt = 0; nt < 8; nt++) {
            csum[nt][0] = csum[nt][1] = 0.f;
            csq[nt][0]  = csq[nt][1]  = 0.f;
        }
    }
#pragma unroll
    for (int nt = 0; nt < 8; nt++) {
        int col0 = nBase + nt * 8 + 2 * q;
        float b0 = bias[col0], b1 = bias[col0 + 1];
#pragma unroll
        for (int mt = 0; mt < 2; mt++) {
#pragma unroll
            for (int half = 0; half < 2; half++) {
                int r = base_row + mBase + mt * 16 + grp + half * 8;
                if (r < M) {
                    float v0 = acc[mt][nt][2*half + 0] + b0;
                    float v1 = acc[mt][nt][2*half + 1] + b1;
                    if (POST_RELU) { v0 = fmaxf(v0, 0.f); v1 = fmaxf(v1, 0.f); }
                    *(float2*)(out + (size_t)r * 128 + col0) =
                        make_float2(v0, v1);
                    if (STATS) {
                        csum[nt][0] += v0;      csum[nt][1] += v1;
                        csq[nt][0]  += v0 * v0; csq[nt][1]  += v1 * v1;
                    }
                }
            }
        }
    }

    if (STATS) {
        __syncthreads();
        float* ssum = (float*)Ahi;
        float* ssq  = ssum + 128;
        ssum[tid] = 0.f;
        __syncthreads();
#pragma unroll
        for (int nt = 0; nt < 8; nt++) {
            int col0 = nBase + nt * 8 + 2 * q;
            atomicAdd(&ssum[col0],     csum[nt][0]);
            atomicAdd(&ssum[col0 + 1], csum[nt][1]);
            atomicAdd(&ssq[col0],      csq[nt][0]);
            atomicAdd(&ssq[col0 + 1],  csq[nt][1]);
        }
        __syncthreads();
        if (tid < 128) {
            atomicAdd(&stats[tid],       ssum[tid]);
            atomicAdd(&stats[128 + tid], ssq[tid]);
        }
    }
}

__global__ void zero_pool_kernel(float4* __restrict__ pool) {
    int i = blockIdx.x * blockDim.x + threadIdx.x;
    pool[i] = make_float4(0.f, 0.f, 0.f, 0.f);
}

__global__ void pool_scatter_kernel(const float4* __restrict__ x,
                                    float4* __restrict__ pool,
                                    const int* __restrict__ batch,
                                    int N) {
    int n = blockIdx.x * 8 + (threadIdx.x >> 5);
    if (n >= N) return;
    int lane = threadIdx.x & 31;
    int g = batch[n];
    float4 v = x[(size_t)n * 32 + lane];
    red_add_f4(&pool[(size_t)g * 32 + lane], v);
}

__global__ void head2_kernel(const float* __restrict__ Hh,
                             const float* __restrict__ W,
                             const float* __restrict__ b,
                             float* __restrict__ out) {
    __shared__ float row[128];
    int g = blockIdx.x;
    int c = threadIdx.x;
    row[c]      = Hh[(size_t)g * 128 + c];
    row[c + 64] = Hh[(size_t)g * 128 + 64 + c];
    __syncthreads();
    float acc = b[c];
#pragma unroll 8
    for (int k = 0; k < 128; k++) acc = fmaf(row[k], W[k * 64 + c], acc);
    out[(size_t)g * 64 + c] = acc;
}

// ---------------- launcher ----------------
extern "C" void kernel_launch(void* const* d_in, const int* in_sizes, int n_in,
                              void* d_out, int out_size) {
    const float* x    = (const float*)d_in[0];
    const float* cW1  = (const float*)d_in[1];
    const float* cb1  = (const float*)d_in[2];
    const float* cgam = (const float*)d_in[3];
    const float* cbet = (const float*)d_in[4];
    const float* cW2  = (const float*)d_in[5];
    const float* cb2  = (const float*)d_in[6];
    const float* hW1  = (const float*)d_in[7];
    const float* hb1  = (const float*)d_in[8];
    const float* hW2  = (const float*)d_in[9];
    const float* hb2  = (const float*)d_in[10];
    const int* ei    = (const int*)d_in[11];   // [2, E] int32
    const int* batch = (const int*)d_in[12];   // [N]    int32
    float* out = (float*)d_out;

    float *bufX, *bufA, *bufB, *pool, *head, *stats;
    int *deg, *rowptr, *cursor, *csr;
    cudaGetSymbolAddress((void**)&bufX,   g_bufX);
    cudaGetSymbolAddress((void**)&bufA,   g_bufA);
    cudaGetSymbolAddress((void**)&bufB,   g_bufB);
    cudaGetSymbolAddress((void**)&pool,   g_pool);
    cudaGetSymbolAddress((void**)&head,   g_head);
    cudaGetSymbolAddress((void**)&stats,  g_stats);
    cudaGetSymbolAddress((void**)&deg,    g_deg);
    cudaGetSymbolAddress((void**)&rowptr, g_rowptr);
    cudaGetSymbolAddress((void**)&cursor, g_cursor);
    cudaGetSymbolAddress((void**)&csr,    g_csr);

    cudaFuncSetAttribute(gemm_k128<false, false, true>,
                         cudaFuncAttributeMaxDynamicSharedMemorySize,
                         GEMM_SMEM_BYTES);
    cudaFuncSetAttribute(gemm_k128<true, true, false>,
                         cudaFuncAttributeMaxDynamicSharedMemorySize,
                         GEMM_SMEM_BYTES);
    cudaFuncSetAttribute(gemm_k128<false, true, false>,
                         cudaFuncAttributeMaxDynamicSharedMemorySize,
                         GEMM_SMEM_BYTES);

    const int* e_src = ei;
    const int* e_dst = ei + EE;
    const int gemm_blocks = (NN + 127) / 128;  // 391
    const int e4_blocks = (EE / 4 + 255) / 256;  // 782

    // CSR build (deg arrives zeroed; scan re-zeroes it for the next call)
    hist_kernel<<<e4_blocks, 256>>>((const int4*)e_dst, deg);
    scan_kernel<<<1, 1024>>>((int4*)deg, rowptr, cursor);
    fill_kernel<<<e4_blocks, 256>>>((const int4*)e_src, (const int4*)e_dst,
                                    cursor, csr);

    for (int l = 0; l < 3; l++) {
        const float* in = (l == 0) ? x : bufX;
        gather_kernel<<<(NN + 7) / 8, 256>>>(
            (const float4*)in, (float4*)bufA, rowptr, csr, stats);
        gemm_k128<false, false, true><<<gemm_blocks, 256, GEMM_SMEM_BYTES>>>(
            bufA, cW1 + l * HDIM * HDIM, cb1 + l * HDIM,
            nullptr, nullptr, bufB, stats, NN, 0.f);
        gemm_k128<true, true, false><<<gemm_blocks, 256, GEMM_SMEM_BYTES>>>(
            bufB, cW2 + l * HDIM * HDIM, cb2 + l * HDIM,
            cgam + l * HDIM, cbet + l * HDIM, bufX, stats, NN, 1.0f / NN);
    }

    zero_pool_kernel<<<64, 256>>>((float4*)pool);
    pool_scatter_kernel<<<(NN + 7) / 8, 256>>>(
        (const float4*)bufX, (float4*)pool, batch, NN);
    gemm_k128<false, true, false><<<(GG + 127) / 128, 256, GEMM_SMEM_BYTES>>>(
        pool, hW1, hb1, nullptr, nullptr, head, nullptr, GG, 0.f);
    head2_kernel<<<GG, 64>>>(head, hW2, hb2, out);
}

// round 16
// speedup vs baseline: 1.2788x; 1.0681x over previous
#include <cuda_runtime.h>
#include <cuda_bf16.h>
#include <cuda_fp16.h>
#include <cstddef>

#define NN   50000
#define EE   800000
#define HDIM 128
#define GG   512
#define OUTD 64
#define BN_EPS 1e-5f

// ---------------- device scratch (no allocation allowed) ----------------
__device__ __align__(16) float g_bufX[NN * HDIM];
__device__ __align__(16) float g_bufA[NN * HDIM];
__device__ __align__(16) float g_bufB[NN * HDIM];
__device__ __align__(16) float g_pool[GG * HDIM];
__device__ __align__(16) float g_head[GG * HDIM];
__device__ __align__(16) float g_stats[2 * HDIM];
// CSR scratch (deg zero at load; scan_kernel re-zeroes after use)
__device__ __align__(16) int g_deg[NN];
__device__ __align__(16) int g_rowptr[NN + 4];
__device__ __align__(16) int g_cursor[NN];
__device__ int g_csr[EE];

// ---------------- helpers ----------------
__device__ __forceinline__ void red_add_f4(float4* addr, float4 v) {
    asm volatile("red.global.add.v4.f32 [%0], {%1,%2,%3,%4};"
                 :: "l"(addr), "f"(v.x), "f"(v.y), "f"(v.z), "f"(v.w)
                 : "memory");
}

__device__ __forceinline__ void cp_async16(void* smem_dst, const void* gsrc) {
    unsigned d = (unsigned)__cvta_generic_to_shared(smem_dst);
    asm volatile("cp.async.cg.shared.global [%0], [%1], 16;"
                 :: "r"(d), "l"(gsrc));
}
#define CP_COMMIT()  asm volatile("cp.async.commit_group;")
#define CP_WAIT0()   asm volatile("cp.async.wait_group 0;")

// fp16 mma: D(16x8,f32) += A(16x16,f16 row) * B(16x8,f16 col)
__device__ __forceinline__ void mma_fp16(float* d, const unsigned* a,
                                         const unsigned* b) {
    asm volatile(
        "mma.sync.aligned.m16n8k16.row.col.f32.f16.f16.f32 "
        "{%0,%1,%2,%3}, {%4,%5,%6,%7}, {%8,%9}, {%0,%1,%2,%3};"
        : "+f"(d[0]), "+f"(d[1]), "+f"(d[2]), "+f"(d[3])
        : "r"(a[0]), "r"(a[1]), "r"(a[2]), "r"(a[3]), "r"(b[0]), "r"(b[1]));
}

__device__ __forceinline__ unsigned pack_h2(__half a, __half b) {
    return ((unsigned)__half_as_ushort(b) << 16) |
           (unsigned)__half_as_ushort(a);
}

// split v -> (hi, lo) fp16 pair; hi+lo represents v to ~2^-22 relative
__device__ __forceinline__ void split_fp16(float v, __half& hi, __half& lo) {
    hi = __float2half_rn(v);
    lo = __float2half_rn(v - __half2float(hi));
}

// ---------------- CSR build kernels (int4-vectorized, 4 edges/thread) -----
__global__ void hist_kernel(const int4* __restrict__ dst4,
                            int* __restrict__ deg) {
    int i = blockIdx.x * blockDim.x + threadIdx.x;   // EE/4 = 200000 threads
    if (i >= EE / 4) return;
    int4 d = dst4[i];
    atomicAdd(&deg[d.x], 1);
    atomicAdd(&deg[d.y], 1);
    atomicAdd(&deg[d.z], 1);
    atomicAdd(&deg[d.w], 1);
}

// single-block exclusive scan of deg -> rowptr+cursor, int4-vectorized;
// zeroes deg after use (so hist finds it clean on the next call)
__global__ void scan_kernel(int4* __restrict__ deg4,
                            int* __restrict__ rowptr,
                            int* __restrict__ cursor) {
    __shared__ int ssum[1024];
    const int T = 1024, CH4 = 13;          // 13 int4 = 52 ints per thread
    const int n4 = NN / 4;                  // 12500
    int t = threadIdx.x;
    int b4 = t * CH4;
    int e4 = b4 + CH4; if (e4 > n4) e4 = n4;
    int s = 0;
    for (int i = b4; i < e4; i++) {
        int4 v = deg4[i];
        s += v.x + v.y + v.z + v.w;
    }
    ssum[t] = s;
    __syncthreads();
    for (int off = 1; off < T; off <<= 1) {
        int v = (t >= off) ? ssum[t - off] : 0;
        __syncthreads();
        ssum[t] += v;
        __syncthreads();
    }
    int run = (t == 0) ? 0 : ssum[t - 1];
    int4* rp4 = (int4*)rowptr;
    int4* cu4 = (int4*)cursor;
    for (int i = b4; i < e4; i++) {
        int4 v = deg4[i];
        int4 r;
        r.x = run; run += v.x;
        r.y = run; run += v.y;
        r.z = run; run += v.z;
        r.w = run; run += v.w;
        rp4[i] = r;
        cu4[i] = r;
        deg4[i] = make_int4(0, 0, 0, 0);
    }
    if (t == T - 1) rowptr[NN] = ssum[T - 1];
}

__global__ void fill_kernel(const int4* __restrict__ src4,
                            const int4* __restrict__ dst4,
                            int* __restrict__ cursor,
                            int* __restrict__ csr) {
    int i = blockIdx.x * blockDim.x + threadIdx.x;
    if (i >= EE / 4) return;
    int4 s = src4[i];
    int4 d = dst4[i];
    csr[atomicAdd(&cursor[d.x], 1)] = s.x;
    csr[atomicAdd(&cursor[d.y], 1)] = s.y;
    csr[atomicAdd(&cursor[d.z], 1)] = s.z;
    csr[atomicAdd(&cursor[d.w], 1)] = s.w;
}

// ---------------- aggregation: warp per node, gather over CSR ----------------
__global__ void gather_kernel(const float4* __restrict__ x,
                              float4* __restrict__ agg,
                              const int* __restrict__ rowptr,
                              const int* __restrict__ csr,
                              float* __restrict__ stats) {
    if (blockIdx.x == 0 && threadIdx.x < 2 * HDIM) stats[threadIdx.x] = 0.f;
    int n = blockIdx.x * 8 + (threadIdx.x >> 5);
    if (n >= NN) return;
    int lane = threadIdx.x & 31;
    int b = rowptr[n], e = rowptr[n + 1];
    float4 a0 = x[(size_t)n * 32 + lane];
    float4 a1 = make_float4(0.f, 0.f, 0.f, 0.f);
    float4 a2 = make_float4(0.f, 0.f, 0.f, 0.f);
    float4 a3 = make_float4(0.f, 0.f, 0.f, 0.f);
    int i = b;
    for (; i + 4 <= e; i += 4) {
        int s0 = csr[i], s1 = csr[i + 1], s2 = csr[i + 2], s3 = csr[i + 3];
        float4 v0 = x[(size_t)s0 * 32 + lane];
        float4 v1 = x[(size_t)s1 * 32 + lane];
        float4 v2 = x[(size_t)s2 * 32 + lane];
        float4 v3 = x[(size_t)s3 * 32 + lane];
        a0.x += v0.x; a0.y += v0.y; a0.z += v0.z; a0.w += v0.w;
        a1.x += v1.x; a1.y += v1.y; a1.z += v1.z; a1.w += v1.w;
        a2.x += v2.x; a2.y += v2.y; a2.z += v2.z; a2.w += v2.w;
        a3.x += v3.x; a3.y += v3.y; a3.z += v3.z; a3.w += v3.w;
    }
    for (; i < e; i++) {
        float4 v = x[(size_t)csr[i] * 32 + lane];
        a0.x += v.x; a0.y += v.y; a0.z += v.z; a0.w += v.w;
    }
    a0.x += a1.x + a2.x + a3.x;
    a0.y += a1.y + a2.y + a3.y;
    a0.z += a1.z + a2.z + a3.z;
    a0.w += a1.w + a2.w + a3.w;
    agg[(size_t)n * 32 + lane] = a0;
}

// ---------------- GEMM: fp16 2-term split MMA ----------
// D = (Ah + Al) * Wh : A exact via fp16 hi/lo split, W rounded to fp16.
// PRE_BN: derive scale/shift from stats/gamma/beta in-block (BN fold).
// smem: stageA[2][128][16]f @0, Wraw[2][16][128]f @16384,
//       Ahi f16[128][16] @32768, Alo @36864, Wth f16[128][16] @40960,
//       s_scale @45056, s_shift @45568
#define GEMM_SMEM_BYTES 46080

template <bool PRE_BN, bool POST_RELU, bool STATS>
__global__ void __launch_bounds__(256, 2)
gemm_k128(const float* __restrict__ A, const float* __restrict__ W,
          const float* __restrict__ bias, const float* __restrict__ gamma,
          const float* __restrict__ beta, float* __restrict__ out,
          float* __restrict__ stats, int M, float invM) {
    extern __shared__ char smem[];
    float*   stageA = (float*)smem;                 // [2][128][16]
    float*   Wraw   = (float*)(smem + 16384);       // [2][16][128]
    __half*  Ahi    = (__half*)(smem + 32768);
    __half*  Alo    = (__half*)(smem + 36864);
    __half*  Wth    = (__half*)(smem + 40960);
    float*   s_scale = (float*)(smem + 45056);      // [128]
    float*   s_shift = (float*)(smem + 45568);      // [128]

    const int tid  = threadIdx.x;
    const int w    = tid >> 5;
    const int lane = tid & 31;
    const int grp  = lane >> 2;
    const int q    = lane & 3;
    const int mBase = (w & 3) * 32;
    const int nBase = (w >> 2) * 64;
    const int base_row = blockIdx.x * 128;

    if (PRE_BN && tid < 128) {
        float mu   = stats[tid] * invM;
        float var  = stats[128 + tid] * invM - mu * mu;
        float rstd = rsqrtf(var + BN_EPS);
        float sc   = gamma[tid] * rstd;
        s_scale[tid] = sc;
        s_shift[tid] = beta[tid] - mu * sc;
    }

    float acc[2][8][4];
#pragma unroll
    for (int mt = 0; mt < 2; mt++)
#pragma unroll
        for (int nt = 0; nt < 8; nt++)
#pragma unroll
            for (int c = 0; c < 4; c++) acc[mt][nt][c] = 0.f;

    auto issue_tile = [&](int buf, int kb) {
#pragma unroll
        for (int t = 0; t < 2; t++) {
            int idx = tid + t * 256;
            int row = idx >> 2, j = idx & 3;
            int gr  = base_row + row;
            int cgr = gr < M ? gr : 0;
            cp_async16(stageA + buf * 2048 + row * 16 + 4 * j,
                       A + (size_t)cgr * 128 + kb + 4 * j);
        }
#pragma unroll
        for (int t = 0; t < 2; t++) {
            int idx = tid + t * 256;
            int kk = idx >> 5, c = idx & 31;
            cp_async16(Wraw + buf * 2048 + kk * 128 + 4 * c,
                       W + (size_t)(kb + kk) * 128 + 4 * c);
        }
        CP_COMMIT();
    };

    issue_tile(0, 0);

    for (int kb8 = 0; kb8 < 8; kb8++) {
        const int buf = kb8 & 1;
        CP_WAIT0();
        __syncthreads();
        if (kb8 < 7) issue_tile(buf ^ 1, (kb8 + 1) * 16);

        // A transform: f32 -> (hi,lo) fp16, optional BN+ReLU
#pragma unroll
        for (int t = 0; t < 2; t++) {
            int idx = tid + t * 256;
            int row = idx >> 2, j = idx & 3;
            float4 v = *(const float4*)(stageA + buf * 2048 + row * 16 + 4 * j);
            if (PRE_BN) {
                int k = kb8 * 16 + 4 * j;
                v.x = fmaxf(fmaf(v.x, s_scale[k + 0], s_shift[k + 0]), 0.f);
                v.y = fmaxf(fmaf(v.y, s_scale[k + 1], s_shift[k + 1]), 0.f);
                v.z = fmaxf(fmaf(v.z, s_scale[k + 2], s_shift[k + 2]), 0.f);
                v.w = fmaxf(fmaf(v.w, s_scale[k + 3], s_shift[k + 3]), 0.f);
            }
            __half hx,lx,hy,ly,hz,lz,hw,lw;
            split_fp16(v.x,hx,lx); split_fp16(v.y,hy,ly);
            split_fp16(v.z,hz,lz); split_fp16(v.w,hw,lw);
            *(uint2*)(Ahi + row*16 + 4*j) =
                make_uint2(pack_h2(hx,hy), pack_h2(hz,hw));
            *(uint2*)(Alo + row*16 + 4*j) =
                make_uint2(pack_h2(lx,ly), pack_h2(lz,lw));
        }
        // W transform: transpose + single fp16 round
#pragma unroll
        for (int t = 0; t < 2; t++) {
            int idx = tid + t * 256;
            int c = idx & 127, jk = idx >> 7;
            float v0 = Wraw[buf * 2048 + (4*jk+0) * 128 + c];
            float v1 = Wraw[buf * 2048 + (4*jk+1) * 128 + c];
            float v2 = Wraw[buf * 2048 + (4*jk+2) * 128 + c];
            float v3 = Wraw[buf * 2048 + (4*jk+3) * 128 + c];
            *(uint2*)(Wth + c*16 + 4*jk) =
                make_uint2(pack_h2(__float2half_rn(v0), __float2half_rn(v1)),
                           pack_h2(__float2half_rn(v2), __float2half_rn(v3)));
        }
        __syncthreads();

        unsigned ah[2][4], al[2][4];
#pragma unroll
        for (int mt = 0; mt < 2; mt++) {
            int r = mBase + mt * 16 + grp;
            ah[mt][0] = *(const unsigned*)(Ahi + r*16 + 2*q);
            ah[mt][1] = *(const unsigned*)(Ahi + (r+8)*16 + 2*q);
            ah[mt][2] = *(const unsigned*)(Ahi + r*16 + 2*q + 8);
            ah[mt][3] = *(const unsigned*)(Ahi + (r+8)*16 + 2*q + 8);
            al[mt][0] = *(const unsigned*)(Alo + r*16 + 2*q);
            al[mt][1] = *(const unsigned*)(Alo + (r+8)*16 + 2*q);
            al[mt][2] = *(const unsigned*)(Alo + r*16 + 2*q + 8);
            al[mt][3] = *(const unsigned*)(Alo + (r+8)*16 + 2*q + 8);
        }
#pragma unroll
        for (int nt = 0; nt < 8; nt++) {
            int n = nBase + nt * 8 + grp;
            unsigned bh[2];
            bh[0] = *(const unsigned*)(Wth + n*16 + 2*q);
            bh[1] = *(const unsigned*)(Wth + n*16 + 2*q + 8);
#pragma unroll
            for (int mt = 0; mt < 2; mt++) {
                mma_fp16(acc[mt][nt], ah[mt], bh);
                mma_fp16(acc[mt][nt], al[mt], bh);
            }
        }
    }

    float csum[8][2], csq[8][2];
    if (STATS) {
#pragma unroll
        for (int nt = 0; nt < 8; nt++) {
            csum[nt][0] = csum[nt][1] = 0.f;
            csq[nt][0]  = csq[nt][1]  = 0.f;
        }
    }
#pragma unroll
    for (int nt = 0; nt < 8; nt++) {
        int col0 = nBase + nt * 8 + 2 * q;
        float b0 = bias[col0], b1 = bias[col0 + 1];
#pragma unroll
        for (int mt = 0; mt < 2; mt++) {
#pragma unroll
            for (int half = 0; half < 2; half++) {
                int r = base_row + mBase + mt * 16 + grp + half * 8;
                if (r < M) {
                    float v0 = acc[mt][nt][2*half + 0] + b0;
                    float v1 = acc[mt][nt][2*half + 1] + b1;
                    if (POST_RELU) { v0 = fmaxf(v0, 0.f); v1 = fmaxf(v1, 0.f); }
                    *(float2*)(out + (size_t)r * 128 + col0) =
                        make_float2(v0, v1);
                    if (STATS) {
                        csum[nt][0] += v0;      csum[nt][1] += v1;
                        csq[nt][0]  += v0 * v0; csq[nt][1]  += v1 * v1;
                    }
                }
            }
        }
    }

    if (STATS) {
        __syncthreads();
        float* ssum = (float*)Ahi;
        float* ssq  = ssum + 128;
        ssum[tid] = 0.f;
        __syncthreads();
#pragma unroll
        for (int nt = 0; nt < 8; nt++) {
            int col0 = nBase + nt * 8 + 2 * q;
            atomicAdd(&ssum[col0],     csum[nt][0]);
            atomicAdd(&ssum[col0 + 1], csum[nt][1]);
            atomicAdd(&ssq[col0],      csq[nt][0]);
            atomicAdd(&ssq[col0 + 1],  csq[nt][1]);
        }
        __syncthreads();
        if (tid < 128) {
            atomicAdd(&stats[tid],       ssum[tid]);
            atomicAdd(&stats[128 + tid], ssq[tid]);
        }
    }
}

__global__ void zero_pool_kernel(float4* __restrict__ pool) {
    int i = blockIdx.x * blockDim.x + threadIdx.x;
    pool[i] = make_float4(0.f, 0.f, 0.f, 0.f);
}

__global__ void pool_scatter_kernel(const float4* __restrict__ x,
                                    float4* __restrict__ pool,
                                    const int* __restrict__ batch,
                                    int N) {
    int n = blockIdx.x * 8 + (threadIdx.x >> 5);
    if (n >= N) return;
    int lane = threadIdx.x & 31;
    int g = batch[n];
    float4 v = x[(size_t)n * 32 + lane];
    red_add_f4(&pool[(size_t)g * 32 + lane], v);
}

__global__ void head2_kernel(const float* __restrict__ Hh,
                             const float* __restrict__ W,
                             const float* __restrict__ b,
                             float* __restrict__ out) {
    __shared__ float row[128];
    int g = blockIdx.x;
    int c = threadIdx.x;
    row[c]      = Hh[(size_t)g * 128 + c];
    row[c + 64] = Hh[(size_t)g * 128 + 64 + c];
    __syncthreads();
    float acc = b[c];
#pragma unroll 8
    for (int k = 0; k < 128; k++) acc = fmaf(row[k], W[k * 64 + c], acc);
    out[(size_t)g * 64 + c] = acc;
}

// ---------------- launcher ----------------
extern "C" void kernel_launch(void* const* d_in, const int* in_sizes, int n_in,
                              void* d_out, int out_size) {
    const float* x    = (const float*)d_in[0];
    const float* cW1  = (const float*)d_in[1];
    const float* cb1  = (const float*)d_in[2];
    const float* cgam = (const float*)d_in[3];
    const float* cbet = (const float*)d_in[4];
    const float* cW2  = (const float*)d_in[5];
    const float* cb2  = (const float*)d_in[6];
    const float* hW1  = (const float*)d_in[7];
    const float* hb1  = (const float*)d_in[8];
    const float* hW2  = (const float*)d_in[9];
    const float* hb2  = (const float*)d_in[10];
    const int* ei    = (const int*)d_in[11];   // [2, E] int32
    const int* batch = (const int*)d_in[12];   // [N]    int32
    float* out = (float*)d_out;

    float *bufX, *bufA, *bufB, *pool, *head, *stats;
    int *deg, *rowptr, *cursor, *csr;
    cudaGetSymbolAddress((void**)&bufX,   g_bufX);
    cudaGetSymbolAddress((void**)&bufA,   g_bufA);
    cudaGetSymbolAddress((void**)&bufB,   g_bufB);
    cudaGetSymbolAddress((void**)&pool,   g_pool);
    cudaGetSymbolAddress((void**)&head,   g_head);
    cudaGetSymbolAddress((void**)&stats,  g_stats);
    cudaGetSymbolAddress((void**)&deg,    g_deg);
    cudaGetSymbolAddress((void**)&rowptr, g_rowptr);
    cudaGetSymbolAddress((void**)&cursor, g_cursor);
    cudaGetSymbolAddress((void**)&csr,    g_csr);

    cudaFuncSetAttribute(gemm_k128<false, false, true>,
                         cudaFuncAttributeMaxDynamicSharedMemorySize,
                         GEMM_SMEM_BYTES);
    cudaFuncSetAttribute(gemm_k128<true, true, false>,
                         cudaFuncAttributeMaxDynamicSharedMemorySize,
                         GEMM_SMEM_BYTES);
    cudaFuncSetAttribute(gemm_k128<false, true, false>,
                         cudaFuncAttributeMaxDynamicSharedMemorySize,
                         GEMM_SMEM_BYTES);

    const int* e_src = ei;
    const int* e_dst = ei + EE;
    const int gemm_blocks = (NN + 127) / 128;  // 391
    const int e4_blocks = (EE / 4 + 255) / 256;  // 782

    // CSR build (deg arrives zeroed; scan re-zeroes it for the next call)
    hist_kernel<<<e4_blocks, 256>>>((const int4*)e_dst, deg);
    scan_kernel<<<1, 1024>>>((int4*)deg, rowptr, cursor);
    fill_kernel<<<e4_blocks, 256>>>((const int4*)e_src, (const int4*)e_dst,
                                    cursor, csr);

    for (int l = 0; l < 3; l++) {
        const float* in = (l == 0) ? x : bufX;
        gather_kernel<<<(NN + 7) / 8, 256>>>(
            (const float4*)in, (float4*)bufA, rowptr, csr, stats);
        gemm_k128<false, false, true><<<gemm_blocks, 256, GEMM_SMEM_BYTES>>>(
            bufA, cW1 + l * HDIM * HDIM, cb1 + l * HDIM,
            nullptr, nullptr, bufB, stats, NN, 0.f);
        gemm_k128<true, true, false><<<gemm_blocks, 256, GEMM_SMEM_BYTES>>>(
            bufB, cW2 + l * HDIM * HDIM, cb2 + l * HDIM,
            cgam + l * HDIM, cbet + l * HDIM, bufX, stats, NN, 1.0f / NN);
    }

    zero_pool_kernel<<<64, 256>>>((float4*)pool);
    pool_scatter_kernel<<<(NN + 7) / 8, 256>>>(
        (const float4*)bufX, (float4*)pool, batch, NN);
    gemm_k128<false, true, false><<<(GG + 127) / 128, 256, GEMM_SMEM_BYTES>>>(
        pool, hW1, hb1, nullptr, nullptr, head, nullptr, GG, 0.f);
    head2_kernel<<<GG, 64>>>(head, hW2, hb2, out);
}